// round 13
// baseline (speedup 1.0000x reference)
#include <cuda_runtime.h>

#define VOCAB  200000
#define DIM    128
#define NPOS   10
#define NNEG   64
#define NCTX   (NPOS + NNEG)       // 74
#define NROWS  (1 + NPOS + NNEG)   // 75
#define VEC_PER_ROW (VOCAB / 4)    // 50000 float4 per row

#define THREADS 256
#define LOADS   8
#define COVER   (THREADS * LOADS)  // 2048 float4 per block

#define CENTER_VEC (VEC_PER_ROW)            // 12500
#define POS_VEC    (NPOS * VEC_PER_ROW)     // 500000
#define NEG_VEC    (NNEG * VEC_PER_ROW)     // 3200000
#define CB ((CENTER_VEC + COVER - 1) / COVER)   // 7
#define PB ((POS_VEC    + COVER - 1) / COVER)   // 245
#define NB ((NEG_VEC    + COVER - 1) / COVER)   // 1563
#define GRID_A (CB + PB + NB)                   // 1815

// Scratch (alloc-free rule: __device__ globals). Sentinel-initialized.
#define R5  -1,-1,-1,-1,-1
#define R25 R5,R5,R5,R5,R5
__device__ int g_idx[NROWS] = { R25, R25, R25 };   // -1 = not yet found
__device__ float        g_acc  = 0.0f;
__device__ unsigned int g_done = 0u;

// Numerically stable log_sigmoid(x) = -softplus(-x)
__device__ __forceinline__ float log_sigmoidf(float x) {
    return (x >= 0.0f) ? -log1pf(expf(-x)) : (x - log1pf(expf(x)));
}

__device__ __forceinline__ void hit_test(float4 v4, int i, int row_base) {
    // one-hot data is exactly 0.0f / 1.0f -> bitwise test is safe & cheap
    uint4 u = *reinterpret_cast<uint4*>(&v4);
    if ((u.x | u.y | u.z | u.w) != 0u) {            // rare path
        int row = i / VEC_PER_ROW;                  // const-div -> mul
        int vv  = i - row * VEC_PER_ROW;
        int sub = (u.x != 0u) ? 0 : (u.y != 0u) ? 1 : (u.z != 0u) ? 2 : 3;
        // Single-word payload doubles as the ready flag -> plain store.
        g_idx[row_base + row] = 4 * vv + sub;
    }
}

// ---------------------------------------------------------------------------
// Kernel A: stream 60 MB with structural MLP=8. Default (L2-allocating) loads:
// the whole one-hot working set (60 MB) fits in GB300's ~126 MB L2, so timed
// graph replays after the first stream from L2, not HBM. Triggers PDL
// completion at block start so kernel B is resident while A streams.
// ---------------------------------------------------------------------------
__global__ void skipgram_find_idx(const float4* __restrict__ center,
                                  const float4* __restrict__ pos,
                                  const float4* __restrict__ neg) {
    cudaTriggerProgrammaticLaunchCompletion();   // let B come up early

    const int tid = threadIdx.x;
    const int b   = blockIdx.x;

    const float4* base;
    int nvec, row_base, lb;
    if (b < CB)           { base = center; nvec = CENTER_VEC; row_base = 0;        lb = b; }
    else if (b < CB + PB) { base = pos;    nvec = POS_VEC;    row_base = 1;        lb = b - CB; }
    else                  { base = neg;    nvec = NEG_VEC;    row_base = 1 + NPOS; lb = b - CB - PB; }

    const int seg = lb * COVER;
    const int off = seg + tid;

    if (seg + COVER <= nvec) {
        // fast path: branch-free batched loads (MLP=8), L2-allocating
        float4 x[LOADS];
        #pragma unroll
        for (int k = 0; k < LOADS; k++)
            x[k] = __ldg(base + off + k * THREADS);
        #pragma unroll
        for (int k = 0; k < LOADS; k++)
            hit_test(x[k], off + k * THREADS, row_base);
    } else {
        // boundary block: checked loads
        #pragma unroll
        for (int k = 0; k < LOADS; k++) {
            int i = off + k * THREADS;
            if (i < nvec) hit_test(__ldg(base + i), i, row_base);
        }
    }
}

// ---------------------------------------------------------------------------
// Kernel B: 74 blocks x 128 threads, PDL early-launch. Each block spin-waits
// on exactly the two index words it needs (written mid-stream by A), then
// gathers, reduces, accumulates. Last block writes *out and resets state.
// ---------------------------------------------------------------------------
__global__ void skipgram_score(const float* __restrict__ inE,   // [DIM, VOCAB]
                               const float* __restrict__ outE,  // [VOCAB, DIM]
                               float* __restrict__ out) {
    __shared__ int   s_c, s_idx;
    __shared__ float partial[4];

    const int w    = blockIdx.x;          // 0..73
    const int d    = threadIdx.x;         // 0..127
    const int wid  = d >> 5;
    const int lane = d & 31;

    if (d == 0) {
        volatile int* vg = g_idx;
        int c, idx;
        while ((c   = vg[0])     < 0) __nanosleep(64);
        while ((idx = vg[1 + w]) < 0) __nanosleep(64);
        s_c = c; s_idx = idx;
    }
    __syncthreads();
    const int c   = s_c;
    const int idx = s_idx;

    const float vd = inE[(long)d * VOCAB + c];
    const float ud = (w < NPOS) ? inE[(long)d * VOCAB + idx]
                                : outE[(long)idx * DIM + d];

    float dot = vd * ud;
    #pragma unroll
    for (int s = 16; s; s >>= 1) dot += __shfl_xor_sync(0xFFFFFFFFu, dot, s);
    if (lane == 0) partial[wid] = dot;
    __syncthreads();

    if (d == 0) {
        float t = partial[0] + partial[1] + partial[2] + partial[3];
        float x = (w < NPOS) ? t : -t;
        atomicAdd(&g_acc, -log_sigmoidf(x));
        g_idx[1 + w] = -1;               // reset own slot for next replay
        __threadfence();                 // release: acc add + reset visible
        unsigned int old = atomicAdd(&g_done, 1u);
        if (old == NCTX - 1) {
            __threadfence();             // acquire: see all g_acc adds
            *out = *(volatile float*)&g_acc;
            g_acc    = 0.0f;             // reset for next replay
            g_done   = 0u;
            g_idx[0] = -1;               // all blocks have read it by now
        }
    }
}

extern "C" void kernel_launch(void* const* d_in, const int* in_sizes, int n_in,
                              void* d_out, int out_size) {
    const float* center = (const float*)d_in[0];   // [VOCAB]
    const float* pos    = (const float*)d_in[1];   // [NPOS, VOCAB]
    const float* neg    = (const float*)d_in[2];   // [NNEG, VOCAB]
    const float* inE    = (const float*)d_in[3];   // [DIM, VOCAB]
    const float* outE   = (const float*)d_in[4];   // [VOCAB, DIM]
    float* out = (float*)d_out;

    skipgram_find_idx<<<GRID_A, THREADS>>>((const float4*)center,
                                           (const float4*)pos,
                                           (const float4*)neg);

    // Kernel B with PDL: blocks resident while A streams; real dependency is
    // enforced per-word by the sentinel spin inside B.
    cudaLaunchConfig_t cfg = {};
    cfg.gridDim  = dim3(NCTX);
    cfg.blockDim = dim3(DIM);
    cfg.dynamicSmemBytes = 0;
    cfg.stream = 0;
    cudaLaunchAttribute attr[1];
    attr[0].id = cudaLaunchAttributeProgrammaticStreamSerialization;
    attr[0].val.programmaticStreamSerializationAllowed = 1;
    cfg.attrs = attr;
    cfg.numAttrs = 1;
    cudaLaunchKernelEx(&cfg, skipgram_score, inE, outE, out);
}